// round 9
// baseline (speedup 1.0000x reference)
#include <cuda_runtime.h>
#include <cuda_bf16.h>
#include <cstdint>
#include <math.h>

#define BATCH   64
#define TOK     49
#define DIMSZ   768
#define NHEAD   12
#define DHEAD   64
#define FFSZ    3072
#define DEPTH   12
#define MTOK    (BATCH*TOK)     // 3136 = 49*64
#define MPAD    3200            // 25 tiles of 128 (for 128-tile GEMMs)

// ---------------- weight split offsets (elements) ----------------------------
#define OFF_CONV 0
#define SZ_CONV  (768*768)
#define OFF_QKV  (OFF_CONV + SZ_CONV)
#define SZ_QKV   (DEPTH*DIMSZ*3*DIMSZ)
#define OFF_PROJ (OFF_QKV + SZ_QKV)
#define SZ_PROJ  (DEPTH*DIMSZ*DIMSZ)
#define OFF_W1   (OFF_PROJ + SZ_PROJ)
#define SZ_W1    (DEPTH*DIMSZ*FFSZ)
#define OFF_W2   (OFF_W1 + SZ_W1)
#define SZ_W2    (DEPTH*FFSZ*DIMSZ)
#define WTOTAL   (OFF_W2 + SZ_W2)

// ---------------- scratch (device globals) ----------------------------------
__device__ float g_x  [MPAD*DIMSZ];
__device__ float g_qkv[MPAD*3*DIMSZ];
__device__ __nv_bfloat16 g_hh [MPAD*DIMSZ];
__device__ __nv_bfloat16 g_hl [MPAD*DIMSZ];
__device__ __nv_bfloat16 g_ath[MPAD*DIMSZ];
__device__ __nv_bfloat16 g_atl[MPAD*DIMSZ];
__device__ __nv_bfloat16 g_fh [MPAD*FFSZ];
__device__ __nv_bfloat16 g_fl [MPAD*FFSZ];
__device__ __nv_bfloat16 g_wh [WTOTAL];
__device__ __nv_bfloat16 g_wl [WTOTAL];

// ---------------- helpers ----------------------------------------------------
__device__ __forceinline__ uint32_t smem_u32(const void* p) {
    uint32_t a;
    asm("{ .reg .u64 t; cvta.to.shared.u64 t, %1; cvt.u32.u64 %0, t; }" : "=r"(a) : "l"(p));
    return a;
}
#define CP_ASYNC16(dst, src) \
    asm volatile("cp.async.cg.shared.global [%0], [%1], 16;" :: "r"(dst), "l"(src))
#define CP_COMMIT() asm volatile("cp.async.commit_group;" ::: "memory")
#define CP_WAIT1()  asm volatile("cp.async.wait_group 1;" ::: "memory")
#define CP_WAIT0()  asm volatile("cp.async.wait_group 0;" ::: "memory")

__device__ __forceinline__ void ldmx4(uint32_t& r0, uint32_t& r1, uint32_t& r2, uint32_t& r3,
                                      uint32_t addr) {
    asm volatile("ldmatrix.sync.aligned.m8n8.x4.shared.b16 {%0,%1,%2,%3}, [%4];"
                 : "=r"(r0), "=r"(r1), "=r"(r2), "=r"(r3) : "r"(addr));
}
__device__ __forceinline__ void ldmx4t(uint32_t& r0, uint32_t& r1, uint32_t& r2, uint32_t& r3,
                                       uint32_t addr) {
    asm volatile("ldmatrix.sync.aligned.m8n8.x4.trans.shared.b16 {%0,%1,%2,%3}, [%4];"
                 : "=r"(r0), "=r"(r1), "=r"(r2), "=r"(r3) : "r"(addr));
}
__device__ __forceinline__ void mma16816(float* c, const uint32_t* a, uint32_t b0, uint32_t b1) {
    asm volatile("mma.sync.aligned.m16n8k16.row.col.f32.bf16.bf16.f32 "
                 "{%0,%1,%2,%3},{%4,%5,%6,%7},{%8,%9},{%0,%1,%2,%3};"
                 : "+f"(c[0]), "+f"(c[1]), "+f"(c[2]), "+f"(c[3])
                 : "r"(a[0]), "r"(a[1]), "r"(a[2]), "r"(a[3]), "r"(b0), "r"(b1));
}

__device__ __forceinline__ void split1(float x, __nv_bfloat16& h, __nv_bfloat16& l) {
    h = __float2bfloat16(x);
    l = __float2bfloat16(x - __bfloat162float(h));
}
__device__ __forceinline__ float gelu_tanh(float x) {
    float x3 = x * x * x;
    return 0.5f * x * (1.f + tanhf(0.7978845608028654f * (x + 0.044715f * x3)));
}

// ---------------- fused weight split ------------------------------------------
__device__ __forceinline__ void split8(const float* __restrict__ src, size_t di)
{
    uint32_t hp[4], lp[4];
    #pragma unroll
    for (int u = 0; u < 2; u++) {
        float4 v = *(const float4*)(src + u * 4);
        __nv_bfloat16 h0, l0, h1, l1;
        split1(v.x, h0, l0); split1(v.y, h1, l1);
        hp[u*2]   = (uint32_t)__bfloat16_as_ushort(h0) | ((uint32_t)__bfloat16_as_ushort(h1) << 16);
        lp[u*2]   = (uint32_t)__bfloat16_as_ushort(l0) | ((uint32_t)__bfloat16_as_ushort(l1) << 16);
        split1(v.z, h0, l0); split1(v.w, h1, l1);
        hp[u*2+1] = (uint32_t)__bfloat16_as_ushort(h0) | ((uint32_t)__bfloat16_as_ushort(h1) << 16);
        lp[u*2+1] = (uint32_t)__bfloat16_as_ushort(l0) | ((uint32_t)__bfloat16_as_ushort(l1) << 16);
    }
    *(uint4*)(g_wh + di) = make_uint4(hp[0], hp[1], hp[2], hp[3]);
    *(uint4*)(g_wl + di) = make_uint4(lp[0], lp[1], lp[2], lp[3]);
}

__global__ void __launch_bounds__(256) split_a_kernel(const float* __restrict__ conv_w,
                                                      const float* __restrict__ qkv_w)
{
    size_t i = ((size_t)blockIdx.x * 256 + threadIdx.x) * 8;
    if (i >= (size_t)OFF_PROJ) return;
    const float* src = (i < (size_t)SZ_CONV) ? (conv_w + i) : (qkv_w + (i - OFF_QKV));
    split8(src, i);
}
__global__ void __launch_bounds__(256) split_b_kernel(const float* __restrict__ proj_w,
                                                      const float* __restrict__ w1,
                                                      const float* __restrict__ w2)
{
    size_t i = (size_t)OFF_PROJ + ((size_t)blockIdx.x * 256 + threadIdx.x) * 8;
    if (i >= (size_t)WTOTAL) return;
    const float* src;
    if (i < (size_t)OFF_W1)      src = proj_w + (i - OFF_PROJ);
    else if (i < (size_t)OFF_W2) src = w1 + (i - OFF_W1);
    else                         src = w2 + (i - OFF_W2);
    split8(src, i);
}

// ================= 128x128 CTA tile, BK=32 (qkv, ff1) ========================
#define BK32     32
#define B32STR   272
#define B32_TILE (BK32*B32STR)              // 8704
#define A128STR  80
#define A128_TILE (128*A128STR)             // 10240
#define STG128    (2*A128_TILE + 2*B32_TILE)// 37888
#define SMEM_G128 (2*STG128)                // 75776

template<int EPI>
__global__ void __launch_bounds__(256, 2)
gemm_mma128(const __nv_bfloat16* __restrict__ Ah, const __nv_bfloat16* __restrict__ Al,
            const __nv_bfloat16* __restrict__ Wh, const __nv_bfloat16* __restrict__ Wl,
            const float* __restrict__ bias,
            float* __restrict__ C,
            __nv_bfloat16* __restrict__ Chi, __nv_bfloat16* __restrict__ Clo,
            int Mw, int N, int K)
{
    extern __shared__ char smem[];
    uint32_t sb = smem_u32(smem);
    int tid = threadIdx.x, lane = tid & 31, wid = tid >> 5;
    int m0 = blockIdx.y * 128, n0 = blockIdx.x * 128;
    int warpM = (wid & 3) * 32, warpN = (wid >> 2) * 64;

    int arow = tid >> 1, acol = (tid & 1) * 16;
    int brow = tid >> 3, bcol = (tid & 7) * 16;
    const __nv_bfloat16* gAh = Ah + (size_t)(m0 + arow) * K + acol;
    const __nv_bfloat16* gAl = Al + (size_t)(m0 + arow) * K + acol;
    const __nv_bfloat16* gBh = Wh + (size_t)brow * N + n0 + bcol;
    const __nv_bfloat16* gBl = Wl + (size_t)brow * N + n0 + bcol;
    uint32_t sAoff = (uint32_t)arow * A128STR + (uint32_t)acol * 2;
    uint32_t sBoff = (uint32_t)brow * B32STR + (uint32_t)bcol * 2;

    const int nch = K >> 5;

    auto issue = [&](int chunk, int buf) {
        uint32_t st = sb + (uint32_t)buf * STG128;
        const __nv_bfloat16* pAh = gAh + chunk * BK32;
        const __nv_bfloat16* pAl = gAl + chunk * BK32;
        const __nv_bfloat16* pBh = gBh + (size_t)chunk * BK32 * N;
        const __nv_bfloat16* pBl = gBl + (size_t)chunk * BK32 * N;
        CP_ASYNC16(st + sAoff,                      pAh);
        CP_ASYNC16(st + sAoff + 16,                 pAh + 8);
        CP_ASYNC16(st + A128_TILE + sAoff,          pAl);
        CP_ASYNC16(st + A128_TILE + sAoff + 16,     pAl + 8);
        CP_ASYNC16(st + 2*A128_TILE + sBoff,        pBh);
        CP_ASYNC16(st + 2*A128_TILE + sBoff + 16,   pBh + 8);
        CP_ASYNC16(st + 2*A128_TILE + B32_TILE + sBoff,      pBl);
        CP_ASYNC16(st + 2*A128_TILE + B32_TILE + sBoff + 16, pBl + 8);
    };

    issue(0, 0); CP_COMMIT();
    issue(1, 1); CP_COMMIT();

    float acc[2][8][4] = {};

    for (int i = 0; i < nch; i++) {
        if (i + 1 < nch) { CP_WAIT1(); } else { CP_WAIT0(); }
        __syncthreads();
        uint32_t st = sb + (uint32_t)(i & 1) * STG128;

        #pragma unroll
        for (int kk = 0; kk < 2; kk++) {
            uint32_t aAddr = st + (uint32_t)(warpM + (lane & 15)) * A128STR
                               + (uint32_t)kk * 32 + (uint32_t)(lane >> 4) * 16;
            uint32_t ah[2][4], al[2][4];
            ldmx4(ah[0][0], ah[0][1], ah[0][2], ah[0][3], aAddr);
            ldmx4(ah[1][0], ah[1][1], ah[1][2], ah[1][3], aAddr + 16*A128STR);
            ldmx4(al[0][0], al[0][1], al[0][2], al[0][3], aAddr + A128_TILE);
            ldmx4(al[1][0], al[1][1], al[1][2], al[1][3], aAddr + A128_TILE + 16*A128STR);

            #pragma unroll
            for (int nt = 0; nt < 4; nt++) {
                uint32_t bAddr = st + 2*A128_TILE
                    + (uint32_t)(kk*16 + (lane & 15)) * B32STR
                    + (uint32_t)(warpN + nt*16 + (lane >> 4)*8) * 2;
                uint32_t bh[4], bl[4];
                ldmx4t(bh[0], bh[1], bh[2], bh[3], bAddr);
                ldmx4t(bl[0], bl[1], bl[2], bl[3], bAddr + B32_TILE);
                #pragma unroll
                for (int mt = 0; mt < 2; mt++) {
                    mma16816(acc[mt][2*nt+0], ah[mt], bh[0], bh[1]);
                    mma16816(acc[mt][2*nt+1], ah[mt], bh[2], bh[3]);
                    mma16816(acc[mt][2*nt+0], ah[mt], bl[0], bl[1]);
                    mma16816(acc[mt][2*nt+1], ah[mt], bl[2], bl[3]);
                    mma16816(acc[mt][2*nt+0], al[mt], bh[0], bh[1]);
                    mma16816(acc[mt][2*nt+1], al[mt], bh[2], bh[3]);
                }
            }
        }
        __syncthreads();
        if (i + 2 < nch) { issue(i + 2, i & 1); CP_COMMIT(); }
    }

    int r_ = lane >> 2, c_ = (lane & 3) * 2;
    #pragma unroll
    for (int mt = 0; mt < 2; mt++) {
        #pragma unroll
        for (int nt8 = 0; nt8 < 8; nt8++) {
            int row0 = m0 + warpM + mt*16 + r_;
            int col  = n0 + warpN + nt8*8 + c_;
            #pragma unroll
            for (int half = 0; half < 2; half++) {
                int row = row0 + half*8;
                if (row >= Mw) continue;
                float v0 = acc[mt][nt8][half*2 + 0];
                float v1 = acc[mt][nt8][half*2 + 1];
                size_t base = (size_t)row * N + col;
                if (EPI == 0) {
                    *(float2*)(C + base) = make_float2(v0, v1);
                } else {  // gelu(+bias) -> bf16 hi/lo
                    v0 = gelu_tanh(v0 + bias[col]);
                    v1 = gelu_tanh(v1 + bias[col + 1]);
                    __nv_bfloat16 h0, l0, h1, l1;
                    split1(v0, h0, l0); split1(v1, h1, l1);
                    __nv_bfloat162 hv; hv.x = h0; hv.y = h1;
                    __nv_bfloat162 lv; lv.x = l0; lv.y = l1;
                    *(__nv_bfloat162*)(Chi + base) = hv;
                    *(__nv_bfloat162*)(Clo + base) = lv;
                }
            }
        }
    }
}

// ================= 64x128 CTA tile, BK=64 (conv, proj, ff2: N=768) ===========
// Half the sync phases per K: 12 chunks (K=768) / 48 (K=3072).
#define BK64     64
#define A64STR   144                        // 128B data + 16B pad (conflict-free)
#define A64_TILE (64*A64STR)                // 9216
#define B64STR   272
#define B64_TILE (BK64*B64STR)              // 17408
#define STG64    (2*A64_TILE + 2*B64_TILE)  // 53248
#define SMEM_G64 (2*STG64)                  // 106496

template<int EPI>
__global__ void __launch_bounds__(256, 2)
gemm_mma64(const __nv_bfloat16* __restrict__ Ah, const __nv_bfloat16* __restrict__ Al,
           const __nv_bfloat16* __restrict__ Wh, const __nv_bfloat16* __restrict__ Wl,
           const float* __restrict__ bias, const float* __restrict__ res,
           float* __restrict__ C,
           const float* __restrict__ pe_, const int* __restrict__ midx_,
           int N, int K)
{
    extern __shared__ char smem[];
    uint32_t sb = smem_u32(smem);
    int tid = threadIdx.x, lane = tid & 31, wid = tid >> 5;
    int m0 = blockIdx.y * 64, n0 = blockIdx.x * 128;
    int warpM = (wid & 3) * 16, warpN = (wid >> 2) * 64;

    int arow = tid >> 2, acol = (tid & 3) * 16;   // A: 64 rows x 64 k, 16 elems/thr
    int brow = tid >> 2, bcol = (tid & 3) * 32;   // B: 64 rows x 128 n, 32 elems/thr
    const __nv_bfloat16* gAh = Ah + (size_t)(m0 + arow) * K + acol;
    const __nv_bfloat16* gAl = Al + (size_t)(m0 + arow) * K + acol;
    const __nv_bfloat16* gBh = Wh + (size_t)brow * N + n0 + bcol;
    const __nv_bfloat16* gBl = Wl + (size_t)brow * N + n0 + bcol;
    uint32_t sAoff = (uint32_t)arow * A64STR + (uint32_t)acol * 2;
    uint32_t sBoff = (uint32_t)brow * B64STR + (uint32_t)bcol * 2;

    const int nch = K >> 6;

    auto issue = [&](int chunk, int buf) {
        uint32_t st = sb + (uint32_t)buf * STG64;
        const __nv_bfloat16* pAh = gAh + chunk * BK64;
        const __nv_bfloat16* pAl = gAl + chunk * BK64;
        const __nv_bfloat16* pBh = gBh + (size_t)chunk * BK64 * N;
        const __nv_bfloat16* pBl = gBl + (size_t)chunk * BK64 * N;
        CP_ASYNC16(st + sAoff,               pAh);
        CP_ASYNC16(st + sAoff + 16,          pAh + 8);
        CP_ASYNC16(st + A64_TILE + sAoff,      pAl);
        CP_ASYNC16(st + A64_TILE + sAoff + 16, pAl + 8);
        uint32_t bb = st + 2*A64_TILE;
        #pragma unroll
        for (int u = 0; u < 4; u++) {
            CP_ASYNC16(bb + sBoff + u*16,            pBh + u*8);
            CP_ASYNC16(bb + B64_TILE + sBoff + u*16, pBl + u*8);
        }
    };

    issue(0, 0); CP_COMMIT();
    issue(1, 1); CP_COMMIT();          // nch >= 12 always

    float acc[8][4] = {};

    for (int i = 0; i < nch; i++) {
        if (i + 1 < nch) { CP_WAIT1(); } else { CP_WAIT0(); }
        __syncthreads();
        uint32_t st = sb + (uint32_t)(i & 1) * STG64;

        #pragma unroll
        for (int kk = 0; kk < 4; kk++) {
            uint32_t aAddr = st + (uint32_t)(warpM + (lane & 15)) * A64STR
                               + (uint32_t)kk * 32 + (uint32_t)(lane >> 4) * 16;
            uint32_t ah[4], al[4];
            ldmx4(ah[0], ah[1], ah[2], ah[3], aAddr);
            ldmx4(al[0], al[1], al[2], al[3], aAddr + A64_TILE);

            #pragma unroll
            for (int nt = 0; nt < 4; nt++) {
                uint32_t bAddr = st + 2*A64_TILE
                    + (uint32_t)(kk*16 + (lane & 15)) * B64STR
                    + (uint32_t)(warpN + nt*16 + (lane >> 4)*8) * 2;
                uint32_t bh[4], bl[4];
                ldmx4t(bh[0], bh[1], bh[2], bh[3], bAddr);
                ldmx4t(bl[0], bl[1], bl[2], bl[3], bAddr + B64_TILE);
                mma16816(acc[2*nt+0], ah, bh[0], bh[1]);
                mma16816(acc[2*nt+1], ah, bh[2], bh[3]);
                mma16816(acc[2*nt+0], ah, bl[0], bl[1]);
                mma16816(acc[2*nt+1], ah, bl[2], bl[3]);
                mma16816(acc[2*nt+0], al, bh[0], bh[1]);
                mma16816(acc[2*nt+1], al, bh[2], bh[3]);
            }
        }
        __syncthreads();
        if (i + 2 < nch) { issue(i + 2, i & 1); CP_COMMIT(); }
    }

    int r_ = lane >> 2, c_ = (lane & 3) * 2;
    #pragma unroll
    for (int nt8 = 0; nt8 < 8; nt8++) {
        int row0 = m0 + warpM + r_;
        int col  = n0 + warpN + nt8*8 + c_;
        #pragma unroll
        for (int half = 0; half < 2; half++) {
            int row = row0 + half*8;
            float v0 = acc[nt8][half*2 + 0];
            float v1 = acc[nt8][half*2 + 1];
            size_t base = (size_t)row * N + col;
            if (EPI == 1) {         // +res
                float2 r2 = *(const float2*)(res + base);
                *(float2*)(C + base) = make_float2(v0 + r2.x, v1 + r2.y);
            } else if (EPI == 3) {  // +bias +res
                float2 r2 = *(const float2*)(res + base);
                *(float2*)(C + base) = make_float2(v0 + bias[col] + r2.x,
                                                   v1 + bias[col+1] + r2.y);
            } else {                // EPI 4: conv embed + pe gather
                int t = row % TOK;
                int idx = min(max(midx_[t], 0), 196);
                const float* per = pe_ + (size_t)idx * DIMSZ;
                *(float2*)(C + base) = make_float2(v0 + per[col], v1 + per[col+1]);
            }
        }
    }
}

// ---------------- patch gather -> bf16 hi/lo ---------------------------------
__global__ void gather_patches_kernel(const float* __restrict__ inp,
                                      const int* __restrict__ mask_idx)
{
    int blk = blockIdx.x;
    int b = blk / TOK, t = blk % TOK;
    int tid = threadIdx.x;
    int idx = min(max(mask_idx[t], 1), 196);
    int p = idx - 1;
    int ph = p / 14, pw = p % 14;
    const float* base = inp + (((size_t)b * 224 + (size_t)ph * 16) * 224 + (size_t)pw * 16) * 3;
    size_t ob = (size_t)blk * DIMSZ;
    for (int k = tid; k < 768; k += 256) {
        int ij = k / 3, c = k % 3;
        int i = ij / 16, j = ij % 16;
        float v = base[((size_t)i * 224 + j) * 3 + c];
        __nv_bfloat16 h, l;
        split1(v, h, l);
        g_ath[ob + k] = h;
        g_atl[ob + k] = l;
    }
}

// ---------------- layernorm: 192 thr, float4/thread --------------------------
__global__ void __launch_bounds__(192) layernorm_kernel(
        const float* __restrict__ x,
        const float* __restrict__ sc,
        const float* __restrict__ bi,
        __nv_bfloat16* __restrict__ oh,
        __nv_bfloat16* __restrict__ ol)
{
    int row = blockIdx.x;
    int tid = threadIdx.x;
    __shared__ float r1[6], r2[6];

    const float* xr = x + (size_t)row * DIMSZ;
    float4 v = *(const float4*)(xr + tid * 4);
    float s  = v.x + v.y + v.z + v.w;
    float s2 = v.x*v.x + v.y*v.y + v.z*v.z + v.w*v.w;
    #pragma unroll
    for (int o = 16; o; o >>= 1) {
        s  += __shfl_xor_sync(0xffffffffu, s,  o);
        s2 += __shfl_xor_sync(0xffffffffu, s2, o);
    }
    if ((tid & 31) == 0) { r1[tid >> 5] = s; r2[tid >> 5] = s2; }
    __syncthreads();
    float a = 0.f, bsum = 0.f;
    #pragma unroll
    for (int i = 0; i < 6; i++) { a += r1[i]; bsum += r2[i]; }
    float m = a * (1.f / DIMSZ);
    float var = fmaxf(bsum * (1.f / DIMSZ) - m * m, 0.f);
    float inv = rsqrtf(var + 1e-9f);

    float4 sv = *(const float4*)(sc + tid * 4);
    float4 bv = *(const float4*)(bi + tid * 4);
    float o0 = (v.x - m) * inv * sv.x + bv.x;
    float o1 = (v.y - m) * inv * sv.y + bv.y;
    float o2 = (v.z - m) * inv * sv.z + bv.z;
    float o3 = (v.w - m) * inv * sv.w + bv.w;

    __nv_bfloat16 h0,l0,h1,l1,h2,l2,h3,l3;
    split1(o0,h0,l0); split1(o1,h1,l1); split1(o2,h2,l2); split1(o3,h3,l3);
    uint32_t hlo = (uint32_t)__bfloat16_as_ushort(h0) | ((uint32_t)__bfloat16_as_ushort(h1) << 16);
    uint32_t hhi = (uint32_t)__bfloat16_as_ushort(h2) | ((uint32_t)__bfloat16_as_ushort(h3) << 16);
    uint32_t llo = (uint32_t)__bfloat16_as_ushort(l0) | ((uint32_t)__bfloat16_as_ushort(l1) << 16);
    uint32_t lhi = (uint32_t)__bfloat16_as_ushort(l2) | ((uint32_t)__bfloat16_as_ushort(l3) << 16);
    size_t ob = (size_t)row * DIMSZ + tid * 4;
    *(uint2*)(oh + ob) = make_uint2(hlo, hhi);
    *(uint2*)(ol + ob) = make_uint2(llo, lhi);
}

// ---------------- attention: block per (b,h) ---------------------------------
__global__ void __launch_bounds__(256, 4) attention_kernel()
{
    int bh = blockIdx.x;
    int b = bh / NHEAD, h = bh % NHEAD;
    int tid = threadIdx.x;
    int wid = tid >> 5, lid = tid & 31;

    __shared__ float qs[TOK][DHEAD + 1];
    __shared__ float ks[TOK][DHEAD + 1];
    __shared__ float vs[TOK][DHEAD + 1];
    __shared__ float ps[TOK][TOK + 1];

    for (int e = tid; e < TOK * DHEAD; e += 256) {
        int t = e / DHEAD, d = e % DHEAD;
        size_t rb = (size_t)(b * TOK + t) * (3 * DIMSZ) + (size_t)h * DHEAD + d;
        qs[t][d] = g_qkv[rb];
        ks[t][d] = g_qkv[rb + DIMSZ];
        vs[t][d] = g_qkv[rb + 2 * DIMSZ];
    }
    __syncthreads();

    for (int e = tid; e < TOK * TOK; e += 256) {
        int q = e / TOK, j = e % TOK;
        float acc = 0.f;
        #pragma unroll
        for (int d = 0; d < DHEAD; d++) acc += qs[q][d] * ks[j][d];
        ps[q][j] = acc * 0.125f;
    }
    __syncthreads();

    for (int row = wid; row < TOK; row += 8) {
        float mx = -1e30f;
        for (int j = lid; j < TOK; j += 32) mx = fmaxf(mx, ps[row][j]);
        #pragma unroll
        for (int o = 16; o; o >>= 1) mx = fmaxf(mx, __shfl_xor_sync(0xffffffffu, mx, o));
        float sum = 0.f, e0 = 0.f, e1 = 0.f;
        if (lid < TOK)      { e0 = expf(ps[row][lid] - mx);      sum += e0; }
        if (lid + 32 < TOK) { e1 = expf(ps[row][lid + 32] - mx); sum += e1; }
        #pragma unroll
        for (int o = 16; o; o >>= 1) sum += __shfl_xor_sync(0xffffffffu, sum, o);
        float inv = 1.f / sum;
        if (lid < TOK)      ps[row][lid]      = e0 * inv;
        if (lid + 32 < TOK) ps[row][lid + 32] = e1 * inv;
    }
    __syncthreads();

    for (int e = tid; e < TOK * DHEAD; e += 256) {
        int q = e / DHEAD, d = e % DHEAD;
        float acc = 0.f;
        #pragma unroll
        for (int j = 0; j < TOK; j++) acc += ps[q][j] * vs[j][d];
        size_t ob = (size_t)(b * TOK + q) * DIMSZ + (size_t)h * DHEAD + d;
        __nv_bfloat16 hi, lo;
        split1(acc, hi, lo);
        g_ath[ob] = hi;
        g_atl[ob] = lo;
    }
}

// ---------------- launcher ---------------------------------------------------
extern "C" void kernel_launch(void* const* d_in, const int* in_sizes, int n_in,
                              void* d_out, int out_size)
{
    const float* inputs  = (const float*)d_in[0];
    const float* conv_w  = (const float*)d_in[1];
    const float* pe      = (const float*)d_in[3];
    const float* ln1_s   = (const float*)d_in[4];
    const float* ln1_b   = (const float*)d_in[5];
    const float* qkv_w   = (const float*)d_in[6];
    const float* proj_w  = (const float*)d_in[7];
    const float* ln2_s   = (const float*)d_in[8];
    const float* ln2_b   = (const float*)d_in[9];
    const float* w1      = (const float*)d_in[10];
    const float* b1      = (const float*)d_in[11];
    const float* w2      = (const float*)d_in[12];
    const float* b2      = (const float*)d_in[13];
    const int*   mask_idx= (const int*)  d_in[14];
    float* out = (float*)d_out;

    cudaFuncSetAttribute(gemm_mma128<0>, cudaFuncAttributeMaxDynamicSharedMemorySize, SMEM_G128);
    cudaFuncSetAttribute(gemm_mma128<2>, cudaFuncAttributeMaxDynamicSharedMemorySize, SMEM_G128);
    cudaFuncSetAttribute(gemm_mma64<1>,  cudaFuncAttributeMaxDynamicSharedMemorySize, SMEM_G64);
    cudaFuncSetAttribute(gemm_mma64<3>,  cudaFuncAttributeMaxDynamicSharedMemorySize, SMEM_G64);
    cudaFuncSetAttribute(gemm_mma64<4>,  cudaFuncAttributeMaxDynamicSharedMemorySize, SMEM_G64);

    float *xbuf, *qkvbuf;
    __nv_bfloat16 *hh, *hl, *ath, *atl, *fh, *fl, *wh, *wl;
    cudaGetSymbolAddress((void**)&xbuf,  g_x);
    cudaGetSymbolAddress((void**)&qkvbuf,g_qkv);
    cudaGetSymbolAddress((void**)&hh,  g_hh);
    cudaGetSymbolAddress((void**)&hl,  g_hl);
    cudaGetSymbolAddress((void**)&ath, g_ath);
    cudaGetSymbolAddress((void**)&atl, g_atl);
    cudaGetSymbolAddress((void**)&fh,  g_fh);
    cudaGetSymbolAddress((void**)&fl,  g_fl);
    cudaGetSymbolAddress((void**)&wh,  g_wh);
    cudaGetSymbolAddress((void**)&wl,  g_wl);

    dim3 g64(DIMSZ / 128, MTOK / 64);       // (6, 49)
    dim3 gqkv(3 * DIMSZ / 128, MPAD / 128); // (18, 25)
    dim3 gff1(FFSZ / 128, MPAD / 128);      // (24, 25)

    // order: ncu's #6 == our #4 == conv GEMM (64-tile, now BK=64)
    split_a_kernel<<<((size_t)OFF_PROJ/8 + 255)/256, 256>>>(conv_w, qkv_w);
    split_b_kernel<<<(((size_t)WTOTAL - OFF_PROJ)/8 + 255)/256, 256>>>(proj_w, w1, w2);
    gather_patches_kernel<<<MTOK, 256>>>(inputs, mask_idx);
    gemm_mma64<4><<<g64, 256, SMEM_G64>>>(ath, atl, wh + OFF_CONV, wl + OFF_CONV,
                                          nullptr, nullptr, xbuf, pe, mask_idx,
                                          DIMSZ, DIMSZ);

    for (int l = 0; l < DEPTH; l++) {
        layernorm_kernel<<<MTOK, 192>>>(xbuf, ln1_s + (size_t)l * DIMSZ,
                                        ln1_b + (size_t)l * DIMSZ, hh, hl);
        gemm_mma128<0><<<gqkv, 256, SMEM_G128>>>(hh, hl,
                    wh + OFF_QKV + (size_t)l * DIMSZ * 3 * DIMSZ,
                    wl + OFF_QKV + (size_t)l * DIMSZ * 3 * DIMSZ,
                    nullptr, qkvbuf, nullptr, nullptr,
                    MPAD, 3 * DIMSZ, DIMSZ);

        attention_kernel<<<BATCH * NHEAD, 256>>>();

        gemm_mma64<1><<<g64, 256, SMEM_G64>>>(ath, atl,
                    wh + OFF_PROJ + (size_t)l * DIMSZ * DIMSZ,
                    wl + OFF_PROJ + (size_t)l * DIMSZ * DIMSZ,
                    nullptr, xbuf, xbuf, nullptr, nullptr,
                    DIMSZ, DIMSZ);

        layernorm_kernel<<<MTOK, 192>>>(xbuf, ln2_s + (size_t)l * DIMSZ,
                                        ln2_b + (size_t)l * DIMSZ, hh, hl);

        gemm_mma128<2><<<gff1, 256, SMEM_G128>>>(hh, hl,
                    wh + OFF_W1 + (size_t)l * DIMSZ * FFSZ,
                    wl + OFF_W1 + (size_t)l * DIMSZ * FFSZ,
                    b1 + (size_t)l * FFSZ, nullptr, fh, fl,
                    MPAD, FFSZ, DIMSZ);

        float* cdst = (l == DEPTH - 1) ? out : xbuf;
        gemm_mma64<3><<<g64, 256, SMEM_G64>>>(fh, fl,
                    wh + OFF_W2 + (size_t)l * FFSZ * DIMSZ,
                    wl + OFF_W2 + (size_t)l * FFSZ * DIMSZ,
                    b2 + (size_t)l * DIMSZ, xbuf, cdst, nullptr, nullptr,
                    DIMSZ, FFSZ);
    }
}

// round 10
// speedup vs baseline: 1.0940x; 1.0940x over previous
#include <cuda_runtime.h>
#include <cuda_bf16.h>
#include <cstdint>
#include <math.h>

#define BATCH   64
#define TOK     49
#define DIMSZ   768
#define NHEAD   12
#define DHEAD   64
#define FFSZ    3072
#define DEPTH   12
#define MTOK    (BATCH*TOK)     // 3136
#define MPAD    3200            // 25 tiles of 128

// ---------------- weight split offsets (elements) ----------------------------
#define OFF_CONV 0
#define SZ_CONV  (768*768)
#define OFF_QKV  (OFF_CONV + SZ_CONV)
#define SZ_QKV   (DEPTH*DIMSZ*3*DIMSZ)
#define OFF_PROJ (OFF_QKV + SZ_QKV)
#define SZ_PROJ  (DEPTH*DIMSZ*DIMSZ)
#define OFF_W1   (OFF_PROJ + SZ_PROJ)
#define SZ_W1    (DEPTH*DIMSZ*FFSZ)
#define OFF_W2   (OFF_W1 + SZ_W1)
#define SZ_W2    (DEPTH*FFSZ*DIMSZ)
#define WTOTAL   (OFF_W2 + SZ_W2)

// ---------------- scratch (device globals) ----------------------------------
__device__ float g_x  [MPAD*DIMSZ];
__device__ float g_qkv[MPAD*3*DIMSZ];
__device__ float g_part[2*MPAD*DIMSZ];             // split-K partials
__device__ __nv_bfloat16 g_hh [MPAD*DIMSZ];
__device__ __nv_bfloat16 g_hl [MPAD*DIMSZ];
__device__ __nv_bfloat16 g_ath[MPAD*DIMSZ];
__device__ __nv_bfloat16 g_atl[MPAD*DIMSZ];
__device__ __nv_bfloat16 g_fh [MPAD*FFSZ];
__device__ __nv_bfloat16 g_fl [MPAD*FFSZ];
__device__ __nv_bfloat16 g_wh [WTOTAL];
__device__ __nv_bfloat16 g_wl [WTOTAL];

// ---------------- helpers ----------------------------------------------------
__device__ __forceinline__ uint32_t smem_u32(const void* p) {
    uint32_t a;
    asm("{ .reg .u64 t; cvta.to.shared.u64 t, %1; cvt.u32.u64 %0, t; }" : "=r"(a) : "l"(p));
    return a;
}
#define CP_ASYNC16(dst, src) \
    asm volatile("cp.async.cg.shared.global [%0], [%1], 16;" :: "r"(dst), "l"(src))
#define CP_COMMIT() asm volatile("cp.async.commit_group;" ::: "memory")
#define CP_WAIT1()  asm volatile("cp.async.wait_group 1;" ::: "memory")
#define CP_WAIT0()  asm volatile("cp.async.wait_group 0;" ::: "memory")

__device__ __forceinline__ void ldmx4(uint32_t& r0, uint32_t& r1, uint32_t& r2, uint32_t& r3,
                                      uint32_t addr) {
    asm volatile("ldmatrix.sync.aligned.m8n8.x4.shared.b16 {%0,%1,%2,%3}, [%4];"
                 : "=r"(r0), "=r"(r1), "=r"(r2), "=r"(r3) : "r"(addr));
}
__device__ __forceinline__ void ldmx4t(uint32_t& r0, uint32_t& r1, uint32_t& r2, uint32_t& r3,
                                       uint32_t addr) {
    asm volatile("ldmatrix.sync.aligned.m8n8.x4.trans.shared.b16 {%0,%1,%2,%3}, [%4];"
                 : "=r"(r0), "=r"(r1), "=r"(r2), "=r"(r3) : "r"(addr));
}
__device__ __forceinline__ void mma16816(float* c, const uint32_t* a, uint32_t b0, uint32_t b1) {
    asm volatile("mma.sync.aligned.m16n8k16.row.col.f32.bf16.bf16.f32 "
                 "{%0,%1,%2,%3},{%4,%5,%6,%7},{%8,%9},{%0,%1,%2,%3};"
                 : "+f"(c[0]), "+f"(c[1]), "+f"(c[2]), "+f"(c[3])
                 : "r"(a[0]), "r"(a[1]), "r"(a[2]), "r"(a[3]), "r"(b0), "r"(b1));
}

__device__ __forceinline__ void split1(float x, __nv_bfloat16& h, __nv_bfloat16& l) {
    h = __float2bfloat16(x);
    l = __float2bfloat16(x - __bfloat162float(h));
}
__device__ __forceinline__ float gelu_tanh(float x) {
    float x3 = x * x * x;
    return 0.5f * x * (1.f + tanhf(0.7978845608028654f * (x + 0.044715f * x3)));
}

// ---------------- fused weight split ------------------------------------------
__device__ __forceinline__ void split8(const float* __restrict__ src, size_t di)
{
    uint32_t hp[4], lp[4];
    #pragma unroll
    for (int u = 0; u < 2; u++) {
        float4 v = *(const float4*)(src + u * 4);
        __nv_bfloat16 h0, l0, h1, l1;
        split1(v.x, h0, l0); split1(v.y, h1, l1);
        hp[u*2]   = (uint32_t)__bfloat16_as_ushort(h0) | ((uint32_t)__bfloat16_as_ushort(h1) << 16);
        lp[u*2]   = (uint32_t)__bfloat16_as_ushort(l0) | ((uint32_t)__bfloat16_as_ushort(l1) << 16);
        split1(v.z, h0, l0); split1(v.w, h1, l1);
        hp[u*2+1] = (uint32_t)__bfloat16_as_ushort(h0) | ((uint32_t)__bfloat16_as_ushort(h1) << 16);
        lp[u*2+1] = (uint32_t)__bfloat16_as_ushort(l0) | ((uint32_t)__bfloat16_as_ushort(l1) << 16);
    }
    *(uint4*)(g_wh + di) = make_uint4(hp[0], hp[1], hp[2], hp[3]);
    *(uint4*)(g_wl + di) = make_uint4(lp[0], lp[1], lp[2], lp[3]);
}

__global__ void __launch_bounds__(256) split_a_kernel(const float* __restrict__ conv_w,
                                                      const float* __restrict__ qkv_w)
{
    size_t i = ((size_t)blockIdx.x * 256 + threadIdx.x) * 8;
    if (i >= (size_t)OFF_PROJ) return;
    const float* src = (i < (size_t)SZ_CONV) ? (conv_w + i) : (qkv_w + (i - OFF_QKV));
    split8(src, i);
}
__global__ void __launch_bounds__(256) split_b_kernel(const float* __restrict__ proj_w,
                                                      const float* __restrict__ w1,
                                                      const float* __restrict__ w2)
{
    size_t i = (size_t)OFF_PROJ + ((size_t)blockIdx.x * 256 + threadIdx.x) * 8;
    if (i >= (size_t)WTOTAL) return;
    const float* src;
    if (i < (size_t)OFF_W1)      src = proj_w + (i - OFF_PROJ);
    else if (i < (size_t)OFF_W2) src = w1 + (i - OFF_W1);
    else                         src = w2 + (i - OFF_W2);
    split8(src, i);
}

// ================= 128x128 CTA tile, BK=32 (proven mainloop) =================
// EPI 0: plain f32   2: gelu(+bias)->bf16 hi/lo
// SPLITK=1: gridDim.z=2, each CTA does K/2, writes fp32 partial (plain).
#define BK       32
#define ASTRIDE  80
#define BSTRIDE  272
#define A_TILE   (128*ASTRIDE)          // 10240
#define B_TILE   (BK*BSTRIDE)           // 8704
#define STAGE_SZ (2*A_TILE + 2*B_TILE)  // 37888
#define SMEM_GEMM (2*STAGE_SZ)          // 75776

template<int EPI, int SPLITK>
__global__ void __launch_bounds__(256, 2)
gemm_mma128(const __nv_bfloat16* __restrict__ Ah, const __nv_bfloat16* __restrict__ Al,
            const __nv_bfloat16* __restrict__ Wh, const __nv_bfloat16* __restrict__ Wl,
            const float* __restrict__ bias,
            float* __restrict__ C,
            __nv_bfloat16* __restrict__ Chi, __nv_bfloat16* __restrict__ Clo,
            int Mw, int N, int K)
{
    extern __shared__ char smem[];
    uint32_t sb = smem_u32(smem);
    int tid = threadIdx.x, lane = tid & 31, wid = tid >> 5;
    int m0 = blockIdx.y * 128, n0 = blockIdx.x * 128;
    int warpM = (wid & 3) * 32, warpN = (wid >> 2) * 64;

    int kstart = 0;
    if (SPLITK) {
        kstart = blockIdx.z * (K >> 1);
        C += (size_t)blockIdx.z * MPAD * N;
    }
    const int nch = (SPLITK ? (K >> 1) : K) >> 5;

    int arow = tid >> 1, acol = (tid & 1) * 16;
    int brow = tid >> 3, bcol = (tid & 7) * 16;
    const __nv_bfloat16* gAh = Ah + (size_t)(m0 + arow) * K + kstart + acol;
    const __nv_bfloat16* gAl = Al + (size_t)(m0 + arow) * K + kstart + acol;
    const __nv_bfloat16* gBh = Wh + (size_t)(kstart + brow) * N + n0 + bcol;
    const __nv_bfloat16* gBl = Wl + (size_t)(kstart + brow) * N + n0 + bcol;
    uint32_t sAoff = (uint32_t)arow * ASTRIDE + (uint32_t)acol * 2;
    uint32_t sBoff = (uint32_t)brow * BSTRIDE + (uint32_t)bcol * 2;

    auto issue = [&](int chunk, int buf) {
        uint32_t st = sb + (uint32_t)buf * STAGE_SZ;
        const __nv_bfloat16* pAh = gAh + chunk * BK;
        const __nv_bfloat16* pAl = gAl + chunk * BK;
        const __nv_bfloat16* pBh = gBh + (size_t)chunk * BK * N;
        const __nv_bfloat16* pBl = gBl + (size_t)chunk * BK * N;
        CP_ASYNC16(st + sAoff,                   pAh);
        CP_ASYNC16(st + sAoff + 16,              pAh + 8);
        CP_ASYNC16(st + A_TILE + sAoff,          pAl);
        CP_ASYNC16(st + A_TILE + sAoff + 16,     pAl + 8);
        CP_ASYNC16(st + 2*A_TILE + sBoff,        pBh);
        CP_ASYNC16(st + 2*A_TILE + sBoff + 16,   pBh + 8);
        CP_ASYNC16(st + 2*A_TILE + B_TILE + sBoff,      pBl);
        CP_ASYNC16(st + 2*A_TILE + B_TILE + sBoff + 16, pBl + 8);
    };

    issue(0, 0); CP_COMMIT();
    issue(1, 1); CP_COMMIT();          // nch >= 12 always

    float acc[2][8][4] = {};

    for (int i = 0; i < nch; i++) {
        if (i + 1 < nch) { CP_WAIT1(); } else { CP_WAIT0(); }
        __syncthreads();
        uint32_t st = sb + (uint32_t)(i & 1) * STAGE_SZ;

        #pragma unroll
        for (int kk = 0; kk < 2; kk++) {
            uint32_t aAddr = st + (uint32_t)(warpM + (lane & 15)) * ASTRIDE
                               + (uint32_t)kk * 32 + (uint32_t)(lane >> 4) * 16;
            uint32_t ah[2][4], al[2][4];
            ldmx4(ah[0][0], ah[0][1], ah[0][2], ah[0][3], aAddr);
            ldmx4(ah[1][0], ah[1][1], ah[1][2], ah[1][3], aAddr + 16*ASTRIDE);
            ldmx4(al[0][0], al[0][1], al[0][2], al[0][3], aAddr + A_TILE);
            ldmx4(al[1][0], al[1][1], al[1][2], al[1][3], aAddr + A_TILE + 16*ASTRIDE);

            #pragma unroll
            for (int nt = 0; nt < 4; nt++) {
                uint32_t bAddr = st + 2*A_TILE
                    + (uint32_t)(kk*16 + (lane & 15)) * BSTRIDE
                    + (uint32_t)(warpN + nt*16 + (lane >> 4)*8) * 2;
                uint32_t bh[4], bl[4];
                ldmx4t(bh[0], bh[1], bh[2], bh[3], bAddr);
                ldmx4t(bl[0], bl[1], bl[2], bl[3], bAddr + B_TILE);
                #pragma unroll
                for (int mt = 0; mt < 2; mt++) {
                    mma16816(acc[mt][2*nt+0], ah[mt], bh[0], bh[1]);
                    mma16816(acc[mt][2*nt+1], ah[mt], bh[2], bh[3]);
                    mma16816(acc[mt][2*nt+0], ah[mt], bl[0], bl[1]);
                    mma16816(acc[mt][2*nt+1], ah[mt], bl[2], bl[3]);
                    mma16816(acc[mt][2*nt+0], al[mt], bh[0], bh[1]);
                    mma16816(acc[mt][2*nt+1], al[mt], bh[2], bh[3]);
                }
            }
        }
        __syncthreads();
        if (i + 2 < nch) { issue(i + 2, i & 1); CP_COMMIT(); }
    }

    int r_ = lane >> 2, c_ = (lane & 3) * 2;
    #pragma unroll
    for (int mt = 0; mt < 2; mt++) {
        #pragma unroll
        for (int nt8 = 0; nt8 < 8; nt8++) {
            int row0 = m0 + warpM + mt*16 + r_;
            int col  = n0 + warpN + nt8*8 + c_;
            #pragma unroll
            for (int half = 0; half < 2; half++) {
                int row = row0 + half*8;
                if (row >= Mw) continue;
                float v0 = acc[mt][nt8][half*2 + 0];
                float v1 = acc[mt][nt8][half*2 + 1];
                size_t base = (size_t)row * N + col;
                if (EPI == 0) {
                    *(float2*)(C + base) = make_float2(v0, v1);
                } else {  // EPI 2: gelu(+bias) -> bf16 hi/lo
                    v0 = gelu_tanh(v0 + bias[col]);
                    v1 = gelu_tanh(v1 + bias[col + 1]);
                    __nv_bfloat16 h0, l0, h1, l1;
                    split1(v0, h0, l0); split1(v1, h1, l1);
                    __nv_bfloat162 hv; hv.x = h0; hv.y = h1;
                    __nv_bfloat162 lv; lv.x = l0; lv.y = l1;
                    *(__nv_bfloat162*)(Chi + base) = hv;
                    *(__nv_bfloat162*)(Clo + base) = lv;
                }
            }
        }
    }
}

// ---------------- split-K reduce + epilogue (N=768 GEMMs) --------------------
// EPI 1: +res   3: +bias+res   4: +pe gather (conv embed)
template<int EPI>
__global__ void __launch_bounds__(256) reduce_kernel(
        const float* __restrict__ bias, const float* __restrict__ res,
        const float* __restrict__ pe_, const int* __restrict__ midx_,
        float* __restrict__ C)
{
    int gid = blockIdx.x * 256 + threadIdx.x;          // float4 index
    const int total = MTOK * DIMSZ / 4;
    if (gid >= total) return;
    int row  = gid / (DIMSZ / 4);
    int col  = (gid % (DIMSZ / 4)) * 4;
    size_t off = (size_t)row * DIMSZ + col;

    float4 a = *(const float4*)(g_part + off);
    float4 b = *(const float4*)(g_part + (size_t)MPAD * DIMSZ + off);
    float4 v = make_float4(a.x + b.x, a.y + b.y, a.z + b.z, a.w + b.w);

    if (EPI == 1) {
        float4 r = *(const float4*)(res + off);
        v.x += r.x; v.y += r.y; v.z += r.z; v.w += r.w;
    } else if (EPI == 3) {
        float4 r = *(const float4*)(res + off);
        float4 bb = *(const float4*)(bias + col);
        v.x += r.x + bb.x; v.y += r.y + bb.y; v.z += r.z + bb.z; v.w += r.w + bb.w;
    } else {  // EPI 4
        int t = row % TOK;
        int idx = min(max(midx_[t], 0), 196);
        float4 p = *(const float4*)(pe_ + (size_t)idx * DIMSZ + col);
        v.x += p.x; v.y += p.y; v.z += p.z; v.w += p.w;
    }
    *(float4*)(C + off) = v;
}

// ---------------- patch gather -> bf16 hi/lo ---------------------------------
__global__ void gather_patches_kernel(const float* __restrict__ inp,
                                      const int* __restrict__ mask_idx)
{
    int blk = blockIdx.x;
    int b = blk / TOK, t = blk % TOK;
    int tid = threadIdx.x;
    int idx = min(max(mask_idx[t], 1), 196);
    int p = idx - 1;
    int ph = p / 14, pw = p % 14;
    const float* base = inp + (((size_t)b * 224 + (size_t)ph * 16) * 224 + (size_t)pw * 16) * 3;
    size_t ob = (size_t)blk * DIMSZ;
    for (int k = tid; k < 768; k += 256) {
        int ij = k / 3, c = k % 3;
        int i = ij / 16, j = ij % 16;
        float v = base[((size_t)i * 224 + j) * 3 + c];
        __nv_bfloat16 h, l;
        split1(v, h, l);
        g_ath[ob + k] = h;
        g_atl[ob + k] = l;
    }
}

// ---------------- layernorm: 192 thr, float4/thread --------------------------
__global__ void __launch_bounds__(192) layernorm_kernel(
        const float* __restrict__ x,
        const float* __restrict__ sc,
        const float* __restrict__ bi,
        __nv_bfloat16* __restrict__ oh,
        __nv_bfloat16* __restrict__ ol)
{
    int row = blockIdx.x;
    int tid = threadIdx.x;
    __shared__ float r1[6], r2[6];

    const float* xr = x + (size_t)row * DIMSZ;
    float4 v = *(const float4*)(xr + tid * 4);
    float s  = v.x + v.y + v.z + v.w;
    float s2 = v.x*v.x + v.y*v.y + v.z*v.z + v.w*v.w;
    #pragma unroll
    for (int o = 16; o; o >>= 1) {
        s  += __shfl_xor_sync(0xffffffffu, s,  o);
        s2 += __shfl_xor_sync(0xffffffffu, s2, o);
    }
    if ((tid & 31) == 0) { r1[tid >> 5] = s; r2[tid >> 5] = s2; }
    __syncthreads();
    float a = 0.f, bsum = 0.f;
    #pragma unroll
    for (int i = 0; i < 6; i++) { a += r1[i]; bsum += r2[i]; }
    float m = a * (1.f / DIMSZ);
    float var = fmaxf(bsum * (1.f / DIMSZ) - m * m, 0.f);
    float inv = rsqrtf(var + 1e-9f);

    float4 sv = *(const float4*)(sc + tid * 4);
    float4 bv = *(const float4*)(bi + tid * 4);
    float o0 = (v.x - m) * inv * sv.x + bv.x;
    float o1 = (v.y - m) * inv * sv.y + bv.y;
    float o2 = (v.z - m) * inv * sv.z + bv.z;
    float o3 = (v.w - m) * inv * sv.w + bv.w;

    __nv_bfloat16 h0,l0,h1,l1,h2,l2,h3,l3;
    split1(o0,h0,l0); split1(o1,h1,l1); split1(o2,h2,l2); split1(o3,h3,l3);
    uint32_t hlo = (uint32_t)__bfloat16_as_ushort(h0) | ((uint32_t)__bfloat16_as_ushort(h1) << 16);
    uint32_t hhi = (uint32_t)__bfloat16_as_ushort(h2) | ((uint32_t)__bfloat16_as_ushort(h3) << 16);
    uint32_t llo = (uint32_t)__bfloat16_as_ushort(l0) | ((uint32_t)__bfloat16_as_ushort(l1) << 16);
    uint32_t lhi = (uint32_t)__bfloat16_as_ushort(l2) | ((uint32_t)__bfloat16_as_ushort(l3) << 16);
    size_t ob = (size_t)row * DIMSZ + tid * 4;
    *(uint2*)(oh + ob) = make_uint2(hlo, hhi);
    *(uint2*)(ol + ob) = make_uint2(llo, lhi);
}

// ---------------- attention: block per (b,h) ---------------------------------
__global__ void __launch_bounds__(256, 4) attention_kernel()
{
    int bh = blockIdx.x;
    int b = bh / NHEAD, h = bh % NHEAD;
    int tid = threadIdx.x;
    int wid = tid >> 5, lid = tid & 31;

    __shared__ float qs[TOK][DHEAD + 1];
    __shared__ float ks[TOK][DHEAD + 1];
    __shared__ float vs[TOK][DHEAD + 1];
    __shared__ float ps[TOK][TOK + 1];

    for (int e = tid; e < TOK * DHEAD; e += 256) {
        int t = e / DHEAD, d = e % DHEAD;
        size_t rb = (size_t)(b * TOK + t) * (3 * DIMSZ) + (size_t)h * DHEAD + d;
        qs[t][d] = g_qkv[rb];
        ks[t][d] = g_qkv[rb + DIMSZ];
        vs[t][d] = g_qkv[rb + 2 * DIMSZ];
    }
    __syncthreads();

    for (int e = tid; e < TOK * TOK; e += 256) {
        int q = e / TOK, j = e % TOK;
        float acc = 0.f;
        #pragma unroll
        for (int d = 0; d < DHEAD; d++) acc += qs[q][d] * ks[j][d];
        ps[q][j] = acc * 0.125f;
    }
    __syncthreads();

    for (int row = wid; row < TOK; row += 8) {
        float mx = -1e30f;
        for (int j = lid; j < TOK; j += 32) mx = fmaxf(mx, ps[row][j]);
        #pragma unroll
        for (int o = 16; o; o >>= 1) mx = fmaxf(mx, __shfl_xor_sync(0xffffffffu, mx, o));
        float sum = 0.f, e0 = 0.f, e1 = 0.f;
        if (lid < TOK)      { e0 = expf(ps[row][lid] - mx);      sum += e0; }
        if (lid + 32 < TOK) { e1 = expf(ps[row][lid + 32] - mx); sum += e1; }
        #pragma unroll
        for (int o = 16; o; o >>= 1) sum += __shfl_xor_sync(0xffffffffu, sum, o);
        float inv = 1.f / sum;
        if (lid < TOK)      ps[row][lid]      = e0 * inv;
        if (lid + 32 < TOK) ps[row][lid + 32] = e1 * inv;
    }
    __syncthreads();

    for (int e = tid; e < TOK * DHEAD; e += 256) {
        int q = e / DHEAD, d = e % DHEAD;
        float acc = 0.f;
        #pragma unroll
        for (int j = 0; j < TOK; j++) acc += ps[q][j] * vs[j][d];
        size_t ob = (size_t)(b * TOK + q) * DIMSZ + (size_t)h * DHEAD + d;
        __nv_bfloat16 hi, lo;
        split1(acc, hi, lo);
        g_ath[ob] = hi;
        g_atl[ob] = lo;
    }
}

// ---------------- launcher ---------------------------------------------------
extern "C" void kernel_launch(void* const* d_in, const int* in_sizes, int n_in,
                              void* d_out, int out_size)
{
    const float* inputs  = (const float*)d_in[0];
    const float* conv_w  = (const float*)d_in[1];
    const float* pe      = (const float*)d_in[3];
    const float* ln1_s   = (const float*)d_in[4];
    const float* ln1_b   = (const float*)d_in[5];
    const float* qkv_w   = (const float*)d_in[6];
    const float* proj_w  = (const float*)d_in[7];
    const float* ln2_s   = (const float*)d_in[8];
    const float* ln2_b   = (const float*)d_in[9];
    const float* w1      = (const float*)d_in[10];
    const float* b1      = (const float*)d_in[11];
    const float* w2      = (const float*)d_in[12];
    const float* b2      = (const float*)d_in[13];
    const int*   mask_idx= (const int*)  d_in[14];
    float* out = (float*)d_out;

    cudaFuncSetAttribute((const void*)gemm_mma128<0,0>, cudaFuncAttributeMaxDynamicSharedMemorySize, SMEM_GEMM);
    cudaFuncSetAttribute((const void*)gemm_mma128<2,0>, cudaFuncAttributeMaxDynamicSharedMemorySize, SMEM_GEMM);
    cudaFuncSetAttribute((const void*)gemm_mma128<0,1>, cudaFuncAttributeMaxDynamicSharedMemorySize, SMEM_GEMM);

    float *xbuf, *qkvbuf, *part;
    __nv_bfloat16 *hh, *hl, *ath, *atl, *fh, *fl, *wh, *wl;
    cudaGetSymbolAddress((void**)&xbuf,  g_x);
    cudaGetSymbolAddress((void**)&qkvbuf,g_qkv);
    cudaGetSymbolAddress((void**)&part,  g_part);
    cudaGetSymbolAddress((void**)&hh,  g_hh);
    cudaGetSymbolAddress((void**)&hl,  g_hl);
    cudaGetSymbolAddress((void**)&ath, g_ath);
    cudaGetSymbolAddress((void**)&atl, g_atl);
    cudaGetSymbolAddress((void**)&fh,  g_fh);
    cudaGetSymbolAddress((void**)&fl,  g_fl);
    cudaGetSymbolAddress((void**)&wh,  g_wh);
    cudaGetSymbolAddress((void**)&wl,  g_wl);

    dim3 gsk(DIMSZ / 128, MPAD / 128, 2);    // (6, 25, 2) split-K N=768 GEMMs
    dim3 gqkv(3 * DIMSZ / 128, MPAD / 128);  // (18, 25)
    dim3 gff1(FFSZ / 128, MPAD / 128);       // (24, 25)
    const int RED_BLOCKS = (MTOK * DIMSZ / 4 + 255) / 256;

    // order: ncu's #6 == our #4 == conv split-K GEMM
    split_a_kernel<<<((size_t)OFF_PROJ/8 + 255)/256, 256>>>(conv_w, qkv_w);
    split_b_kernel<<<(((size_t)WTOTAL - OFF_PROJ)/8 + 255)/256, 256>>>(proj_w, w1, w2);
    gather_patches_kernel<<<MTOK, 256>>>(inputs, mask_idx);
    gemm_mma128<0,1><<<gsk, 256, SMEM_GEMM>>>(ath, atl, wh + OFF_CONV, wl + OFF_CONV,
                nullptr, part, nullptr, nullptr, MPAD, DIMSZ, DIMSZ);
    reduce_kernel<4><<<RED_BLOCKS, 256>>>(nullptr, nullptr, pe, mask_idx, xbuf);

    for (int l = 0; l < DEPTH; l++) {
        layernorm_kernel<<<MTOK, 192>>>(xbuf, ln1_s + (size_t)l * DIMSZ,
                                        ln1_b + (size_t)l * DIMSZ, hh, hl);
        gemm_mma128<0,0><<<gqkv, 256, SMEM_GEMM>>>(hh, hl,
                    wh + OFF_QKV + (size_t)l * DIMSZ * 3 * DIMSZ,
                    wl + OFF_QKV + (size_t)l * DIMSZ * 3 * DIMSZ,
                    nullptr, qkvbuf, nullptr, nullptr,
                    MPAD, 3 * DIMSZ, DIMSZ);

        attention_kernel<<<BATCH * NHEAD, 256>>>();

        gemm_mma128<0,1><<<gsk, 256, SMEM_GEMM>>>(ath, atl,
                    wh + OFF_PROJ + (size_t)l * DIMSZ * DIMSZ,
                    wl + OFF_PROJ + (size_t)l * DIMSZ * DIMSZ,
                    nullptr, part, nullptr, nullptr, MPAD, DIMSZ, DIMSZ);
        reduce_kernel<1><<<RED_BLOCKS, 256>>>(nullptr, xbuf, nullptr, nullptr, xbuf);

        layernorm_kernel<<<MTOK, 192>>>(xbuf, ln2_s + (size_t)l * DIMSZ,
                                        ln2_b + (size_t)l * DIMSZ, hh, hl);

        gemm_mma128<2,0><<<gff1, 256, SMEM_GEMM>>>(hh, hl,
                    wh + OFF_W1 + (size_t)l * DIMSZ * FFSZ,
                    wl + OFF_W1 + (size_t)l * DIMSZ * FFSZ,
                    b1 + (size_t)l * FFSZ, nullptr, fh, fl,
                    MPAD, FFSZ, DIMSZ);

        gemm_mma128<0,1><<<gsk, 256, SMEM_GEMM>>>(fh, fl,
                    wh + OFF_W2 + (size_t)l * FFSZ * DIMSZ,
                    wl + OFF_W2 + (size_t)l * FFSZ * DIMSZ,
                    nullptr, part, nullptr, nullptr, MPAD, DIMSZ, FFSZ);
        float* cdst = (l == DEPTH - 1) ? out : xbuf;
        reduce_kernel<3><<<RED_BLOCKS, 256>>>(b2 + (size_t)l * DIMSZ, xbuf,
                                              nullptr, nullptr, cdst);
    }
}

// round 11
// speedup vs baseline: 1.1080x; 1.0127x over previous
#include <cuda_runtime.h>
#include <cuda_bf16.h>
#include <cstdint>
#include <math.h>

#define BATCH   64
#define TOK     49
#define DIMSZ   768
#define NHEAD   12
#define DHEAD   64
#define FFSZ    3072
#define DEPTH   12
#define MTOK    (BATCH*TOK)     // 3136
#define MPAD    3200            // 25 tiles of 128

// ---------------- weight split offsets (elements) ----------------------------
#define OFF_CONV 0
#define SZ_CONV  (768*768)
#define OFF_QKV  (OFF_CONV + SZ_CONV)
#define SZ_QKV   (DEPTH*DIMSZ*3*DIMSZ)
#define OFF_PROJ (OFF_QKV + SZ_QKV)
#define SZ_PROJ  (DEPTH*DIMSZ*DIMSZ)
#define OFF_W1   (OFF_PROJ + SZ_PROJ)
#define SZ_W1    (DEPTH*DIMSZ*FFSZ)
#define OFF_W2   (OFF_W1 + SZ_W1)
#define SZ_W2    (DEPTH*FFSZ*DIMSZ)
#define WTOTAL   (OFF_W2 + SZ_W2)

// ---------------- scratch (device globals) ----------------------------------
__device__ float g_x  [MPAD*DIMSZ];
__device__ float g_qkv[MPAD*3*DIMSZ];
__device__ float g_part[2*MPAD*DIMSZ];             // split-K partials
__device__ __nv_bfloat16 g_hh [MPAD*DIMSZ];
__device__ __nv_bfloat16 g_hl [MPAD*DIMSZ];
__device__ __nv_bfloat16 g_ath[MPAD*DIMSZ];
__device__ __nv_bfloat16 g_atl[MPAD*DIMSZ];
__device__ __nv_bfloat16 g_fh [MPAD*FFSZ];
__device__ __nv_bfloat16 g_fl [MPAD*FFSZ];
__device__ __nv_bfloat16 g_wh [WTOTAL];
__device__ __nv_bfloat16 g_wl [WTOTAL];

// ---------------- helpers ----------------------------------------------------
__device__ __forceinline__ uint32_t smem_u32(const void* p) {
    uint32_t a;
    asm("{ .reg .u64 t; cvta.to.shared.u64 t, %1; cvt.u32.u64 %0, t; }" : "=r"(a) : "l"(p));
    return a;
}
#define CP_ASYNC16(dst, src) \
    asm volatile("cp.async.cg.shared.global [%0], [%1], 16;" :: "r"(dst), "l"(src))
#define CP_COMMIT() asm volatile("cp.async.commit_group;" ::: "memory")
#define CP_WAIT1()  asm volatile("cp.async.wait_group 1;" ::: "memory")
#define CP_WAIT0()  asm volatile("cp.async.wait_group 0;" ::: "memory")

__device__ __forceinline__ void ldmx4(uint32_t& r0, uint32_t& r1, uint32_t& r2, uint32_t& r3,
                                      uint32_t addr) {
    asm volatile("ldmatrix.sync.aligned.m8n8.x4.shared.b16 {%0,%1,%2,%3}, [%4];"
                 : "=r"(r0), "=r"(r1), "=r"(r2), "=r"(r3) : "r"(addr));
}
__device__ __forceinline__ void ldmx4t(uint32_t& r0, uint32_t& r1, uint32_t& r2, uint32_t& r3,
                                       uint32_t addr) {
    asm volatile("ldmatrix.sync.aligned.m8n8.x4.trans.shared.b16 {%0,%1,%2,%3}, [%4];"
                 : "=r"(r0), "=r"(r1), "=r"(r2), "=r"(r3) : "r"(addr));
}
__device__ __forceinline__ void mma16816(float* c, const uint32_t* a, uint32_t b0, uint32_t b1) {
    asm volatile("mma.sync.aligned.m16n8k16.row.col.f32.bf16.bf16.f32 "
                 "{%0,%1,%2,%3},{%4,%5,%6,%7},{%8,%9},{%0,%1,%2,%3};"
                 : "+f"(c[0]), "+f"(c[1]), "+f"(c[2]), "+f"(c[3])
                 : "r"(a[0]), "r"(a[1]), "r"(a[2]), "r"(a[3]), "r"(b0), "r"(b1));
}

__device__ __forceinline__ void split1(float x, __nv_bfloat16& h, __nv_bfloat16& l) {
    h = __float2bfloat16(x);
    l = __float2bfloat16(x - __bfloat162float(h));
}
__device__ __forceinline__ float gelu_tanh(float x) {
    float x3 = x * x * x;
    return 0.5f * x * (1.f + tanhf(0.7978845608028654f * (x + 0.044715f * x3)));
}

// ---------------- fused weight split ------------------------------------------
__device__ __forceinline__ void split8(const float* __restrict__ src, size_t di)
{
    uint32_t hp[4], lp[4];
    #pragma unroll
    for (int u = 0; u < 2; u++) {
        float4 v = *(const float4*)(src + u * 4);
        __nv_bfloat16 h0, l0, h1, l1;
        split1(v.x, h0, l0); split1(v.y, h1, l1);
        hp[u*2]   = (uint32_t)__bfloat16_as_ushort(h0) | ((uint32_t)__bfloat16_as_ushort(h1) << 16);
        lp[u*2]   = (uint32_t)__bfloat16_as_ushort(l0) | ((uint32_t)__bfloat16_as_ushort(l1) << 16);
        split1(v.z, h0, l0); split1(v.w, h1, l1);
        hp[u*2+1] = (uint32_t)__bfloat16_as_ushort(h0) | ((uint32_t)__bfloat16_as_ushort(h1) << 16);
        lp[u*2+1] = (uint32_t)__bfloat16_as_ushort(l0) | ((uint32_t)__bfloat16_as_ushort(l1) << 16);
    }
    *(uint4*)(g_wh + di) = make_uint4(hp[0], hp[1], hp[2], hp[3]);
    *(uint4*)(g_wl + di) = make_uint4(lp[0], lp[1], lp[2], lp[3]);
}

__global__ void __launch_bounds__(256) split_a_kernel(const float* __restrict__ conv_w,
                                                      const float* __restrict__ qkv_w)
{
    size_t i = ((size_t)blockIdx.x * 256 + threadIdx.x) * 8;
    if (i >= (size_t)OFF_PROJ) return;
    const float* src = (i < (size_t)SZ_CONV) ? (conv_w + i) : (qkv_w + (i - OFF_QKV));
    split8(src, i);
}
__global__ void __launch_bounds__(256) split_b_kernel(const float* __restrict__ proj_w,
                                                      const float* __restrict__ w1,
                                                      const float* __restrict__ w2)
{
    size_t i = (size_t)OFF_PROJ + ((size_t)blockIdx.x * 256 + threadIdx.x) * 8;
    if (i >= (size_t)WTOTAL) return;
    const float* src;
    if (i < (size_t)OFF_W1)      src = proj_w + (i - OFF_PROJ);
    else if (i < (size_t)OFF_W2) src = w1 + (i - OFF_W1);
    else                         src = w2 + (i - OFF_W2);
    split8(src, i);
}

// ================= 128x128 CTA tile, BK=32 (proven mainloop) =================
// EPI 0: plain f32   2: gelu(+bias)->bf16 hi/lo
// SPLITK=1: gridDim.z=2, each CTA does K/2, writes fp32 partial (plain).
#define BK       32
#define ASTRIDE  80
#define BSTRIDE  272
#define A_TILE   (128*ASTRIDE)          // 10240
#define B_TILE   (BK*BSTRIDE)           // 8704
#define STAGE_SZ (2*A_TILE + 2*B_TILE)  // 37888
#define SMEM_GEMM (2*STAGE_SZ)          // 75776

template<int EPI, int SPLITK>
__global__ void __launch_bounds__(256, 2)
gemm_mma128(const __nv_bfloat16* __restrict__ Ah, const __nv_bfloat16* __restrict__ Al,
            const __nv_bfloat16* __restrict__ Wh, const __nv_bfloat16* __restrict__ Wl,
            const float* __restrict__ bias,
            float* __restrict__ C,
            __nv_bfloat16* __restrict__ Chi, __nv_bfloat16* __restrict__ Clo,
            int Mw, int N, int K)
{
    extern __shared__ char smem[];
    uint32_t sb = smem_u32(smem);
    int tid = threadIdx.x, lane = tid & 31, wid = tid >> 5;
    int m0 = blockIdx.y * 128, n0 = blockIdx.x * 128;
    int warpM = (wid & 3) * 32, warpN = (wid >> 2) * 64;

    int kstart = 0;
    if (SPLITK) {
        kstart = blockIdx.z * (K >> 1);
        C += (size_t)blockIdx.z * MPAD * N;
    }
    const int nch = (SPLITK ? (K >> 1) : K) >> 5;

    int arow = tid >> 1, acol = (tid & 1) * 16;
    int brow = tid >> 3, bcol = (tid & 7) * 16;
    const __nv_bfloat16* gAh = Ah + (size_t)(m0 + arow) * K + kstart + acol;
    const __nv_bfloat16* gAl = Al + (size_t)(m0 + arow) * K + kstart + acol;
    const __nv_bfloat16* gBh = Wh + (size_t)(kstart + brow) * N + n0 + bcol;
    const __nv_bfloat16* gBl = Wl + (size_t)(kstart + brow) * N + n0 + bcol;
    uint32_t sAoff = (uint32_t)arow * ASTRIDE + (uint32_t)acol * 2;
    uint32_t sBoff = (uint32_t)brow * BSTRIDE + (uint32_t)bcol * 2;

    auto issue = [&](int chunk, int buf) {
        uint32_t st = sb + (uint32_t)buf * STAGE_SZ;
        const __nv_bfloat16* pAh = gAh + chunk * BK;
        const __nv_bfloat16* pAl = gAl + chunk * BK;
        const __nv_bfloat16* pBh = gBh + (size_t)chunk * BK * N;
        const __nv_bfloat16* pBl = gBl + (size_t)chunk * BK * N;
        CP_ASYNC16(st + sAoff,                   pAh);
        CP_ASYNC16(st + sAoff + 16,              pAh + 8);
        CP_ASYNC16(st + A_TILE + sAoff,          pAl);
        CP_ASYNC16(st + A_TILE + sAoff + 16,     pAl + 8);
        CP_ASYNC16(st + 2*A_TILE + sBoff,        pBh);
        CP_ASYNC16(st + 2*A_TILE + sBoff + 16,   pBh + 8);
        CP_ASYNC16(st + 2*A_TILE + B_TILE + sBoff,      pBl);
        CP_ASYNC16(st + 2*A_TILE + B_TILE + sBoff + 16, pBl + 8);
    };

    issue(0, 0); CP_COMMIT();
    issue(1, 1); CP_COMMIT();          // nch >= 12 always

    float acc[2][8][4] = {};

    for (int i = 0; i < nch; i++) {
        if (i + 1 < nch) { CP_WAIT1(); } else { CP_WAIT0(); }
        __syncthreads();
        uint32_t st = sb + (uint32_t)(i & 1) * STAGE_SZ;

        #pragma unroll
        for (int kk = 0; kk < 2; kk++) {
            uint32_t aAddr = st + (uint32_t)(warpM + (lane & 15)) * ASTRIDE
                               + (uint32_t)kk * 32 + (uint32_t)(lane >> 4) * 16;
            uint32_t ah[2][4], al[2][4];
            ldmx4(ah[0][0], ah[0][1], ah[0][2], ah[0][3], aAddr);
            ldmx4(ah[1][0], ah[1][1], ah[1][2], ah[1][3], aAddr + 16*ASTRIDE);
            ldmx4(al[0][0], al[0][1], al[0][2], al[0][3], aAddr + A_TILE);
            ldmx4(al[1][0], al[1][1], al[1][2], al[1][3], aAddr + A_TILE + 16*ASTRIDE);

            #pragma unroll
            for (int nt = 0; nt < 4; nt++) {
                uint32_t bAddr = st + 2*A_TILE
                    + (uint32_t)(kk*16 + (lane & 15)) * BSTRIDE
                    + (uint32_t)(warpN + nt*16 + (lane >> 4)*8) * 2;
                uint32_t bh[4], bl[4];
                ldmx4t(bh[0], bh[1], bh[2], bh[3], bAddr);
                ldmx4t(bl[0], bl[1], bl[2], bl[3], bAddr + B_TILE);
                #pragma unroll
                for (int mt = 0; mt < 2; mt++) {
                    mma16816(acc[mt][2*nt+0], ah[mt], bh[0], bh[1]);
                    mma16816(acc[mt][2*nt+1], ah[mt], bh[2], bh[3]);
                    mma16816(acc[mt][2*nt+0], ah[mt], bl[0], bl[1]);
                    mma16816(acc[mt][2*nt+1], ah[mt], bl[2], bl[3]);
                    mma16816(acc[mt][2*nt+0], al[mt], bh[0], bh[1]);
                    mma16816(acc[mt][2*nt+1], al[mt], bh[2], bh[3]);
                }
            }
        }
        __syncthreads();
        if (i + 2 < nch) { issue(i + 2, i & 1); CP_COMMIT(); }
    }

    int r_ = lane >> 2, c_ = (lane & 3) * 2;
    #pragma unroll
    for (int mt = 0; mt < 2; mt++) {
        #pragma unroll
        for (int nt8 = 0; nt8 < 8; nt8++) {
            int row0 = m0 + warpM + mt*16 + r_;
            int col  = n0 + warpN + nt8*8 + c_;
            #pragma unroll
            for (int half = 0; half < 2; half++) {
                int row = row0 + half*8;
                if (row >= Mw) continue;
                float v0 = acc[mt][nt8][half*2 + 0];
                float v1 = acc[mt][nt8][half*2 + 1];
                size_t base = (size_t)row * N + col;
                if (EPI == 0) {
                    *(float2*)(C + base) = make_float2(v0, v1);
                } else {  // EPI 2: gelu(+bias) -> bf16 hi/lo
                    v0 = gelu_tanh(v0 + bias[col]);
                    v1 = gelu_tanh(v1 + bias[col + 1]);
                    __nv_bfloat16 h0, l0, h1, l1;
                    split1(v0, h0, l0); split1(v1, h1, l1);
                    __nv_bfloat162 hv; hv.x = h0; hv.y = h1;
                    __nv_bfloat162 lv; lv.x = l0; lv.y = l1;
                    *(__nv_bfloat162*)(Chi + base) = hv;
                    *(__nv_bfloat162*)(Clo + base) = lv;
                }
            }
        }
    }
}

// ---------------- fused split-K reduce + epilogue + layernorm ----------------
// One block per row (192 threads, float4/thread).
// EPI 0: +pe gather (conv)   1: +res (proj)   2: +bias +res (ff2)
// Always: writes xio (new residual) and LN(sc,bi) -> oh/ol bf16 hi/lo.
template<int EPI>
__global__ void __launch_bounds__(192) reduce_ln_kernel(
        const float* __restrict__ bias,
        const float* __restrict__ pe_, const int* __restrict__ midx_,
        const float* __restrict__ sc, const float* __restrict__ bi,
        float* __restrict__ xio,
        __nv_bfloat16* __restrict__ oh, __nv_bfloat16* __restrict__ ol)
{
    int row = blockIdx.x;
    int tid = threadIdx.x;
    int col = tid * 4;
    size_t off = (size_t)row * DIMSZ + col;
    __shared__ float r1[6], r2[6];

    float4 a = *(const float4*)(g_part + off);
    float4 b = *(const float4*)(g_part + (size_t)MPAD * DIMSZ + off);
    float4 v = make_float4(a.x + b.x, a.y + b.y, a.z + b.z, a.w + b.w);

    if (EPI == 0) {
        int t = row % TOK;
        int idx = min(max(midx_[t], 0), 196);
        float4 p = *(const float4*)(pe_ + (size_t)idx * DIMSZ + col);
        v.x += p.x; v.y += p.y; v.z += p.z; v.w += p.w;
    } else if (EPI == 1) {
        float4 r = *(const float4*)(xio + off);
        v.x += r.x; v.y += r.y; v.z += r.z; v.w += r.w;
    } else {
        float4 r = *(const float4*)(xio + off);
        float4 bb = *(const float4*)(bias + col);
        v.x += r.x + bb.x; v.y += r.y + bb.y; v.z += r.z + bb.z; v.w += r.w + bb.w;
    }
    *(float4*)(xio + off) = v;

    // layernorm stats
    float s  = v.x + v.y + v.z + v.w;
    float s2 = v.x*v.x + v.y*v.y + v.z*v.z + v.w*v.w;
    #pragma unroll
    for (int o = 16; o; o >>= 1) {
        s  += __shfl_xor_sync(0xffffffffu, s,  o);
        s2 += __shfl_xor_sync(0xffffffffu, s2, o);
    }
    if ((tid & 31) == 0) { r1[tid >> 5] = s; r2[tid >> 5] = s2; }
    __syncthreads();
    float su = 0.f, sq = 0.f;
    #pragma unroll
    for (int i = 0; i < 6; i++) { su += r1[i]; sq += r2[i]; }
    float m = su * (1.f / DIMSZ);
    float var = fmaxf(sq * (1.f / DIMSZ) - m * m, 0.f);
    float inv = rsqrtf(var + 1e-9f);

    float4 sv = *(const float4*)(sc + col);
    float4 bv = *(const float4*)(bi + col);
    float o0 = (v.x - m) * inv * sv.x + bv.x;
    float o1 = (v.y - m) * inv * sv.y + bv.y;
    float o2 = (v.z - m) * inv * sv.z + bv.z;
    float o3 = (v.w - m) * inv * sv.w + bv.w;

    __nv_bfloat16 h0,l0,h1,l1,h2,l2,h3,l3;
    split1(o0,h0,l0); split1(o1,h1,l1); split1(o2,h2,l2); split1(o3,h3,l3);
    uint32_t hlo = (uint32_t)__bfloat16_as_ushort(h0) | ((uint32_t)__bfloat16_as_ushort(h1) << 16);
    uint32_t hhi = (uint32_t)__bfloat16_as_ushort(h2) | ((uint32_t)__bfloat16_as_ushort(h3) << 16);
    uint32_t llo = (uint32_t)__bfloat16_as_ushort(l0) | ((uint32_t)__bfloat16_as_ushort(l1) << 16);
    uint32_t lhi = (uint32_t)__bfloat16_as_ushort(l2) | ((uint32_t)__bfloat16_as_ushort(l3) << 16);
    *(uint2*)(oh + off) = make_uint2(hlo, hhi);
    *(uint2*)(ol + off) = make_uint2(llo, lhi);
}

// ---------------- final reduce (+bias +res -> out, no LN) --------------------
__global__ void __launch_bounds__(256) reduce_final_kernel(
        const float* __restrict__ bias, const float* __restrict__ res,
        float* __restrict__ C)
{
    int gid = blockIdx.x * 256 + threadIdx.x;
    const int total = MTOK * DIMSZ / 4;
    if (gid >= total) return;
    int row  = gid / (DIMSZ / 4);
    int col  = (gid % (DIMSZ / 4)) * 4;
    size_t off = (size_t)row * DIMSZ + col;

    float4 a = *(const float4*)(g_part + off);
    float4 b = *(const float4*)(g_part + (size_t)MPAD * DIMSZ + off);
    float4 r = *(const float4*)(res + off);
    float4 bb = *(const float4*)(bias + col);
    float4 v = make_float4(a.x + b.x + r.x + bb.x, a.y + b.y + r.y + bb.y,
                           a.z + b.z + r.z + bb.z, a.w + b.w + r.w + bb.w);
    *(float4*)(C + off) = v;
}

// ---------------- patch gather -> bf16 hi/lo ---------------------------------
__global__ void gather_patches_kernel(const float* __restrict__ inp,
                                      const int* __restrict__ mask_idx)
{
    int blk = blockIdx.x;
    int b = blk / TOK, t = blk % TOK;
    int tid = threadIdx.x;
    int idx = min(max(mask_idx[t], 1), 196);
    int p = idx - 1;
    int ph = p / 14, pw = p % 14;
    const float* base = inp + (((size_t)b * 224 + (size_t)ph * 16) * 224 + (size_t)pw * 16) * 3;
    size_t ob = (size_t)blk * DIMSZ;
    for (int k = tid; k < 768; k += 256) {
        int ij = k / 3, c = k % 3;
        int i = ij / 16, j = ij % 16;
        float v = base[((size_t)i * 224 + j) * 3 + c];
        __nv_bfloat16 h, l;
        split1(v, h, l);
        g_ath[ob + k] = h;
        g_atl[ob + k] = l;
    }
}

// ---------------- attention: block per (b,h) ---------------------------------
__global__ void __launch_bounds__(256, 4) attention_kernel()
{
    int bh = blockIdx.x;
    int b = bh / NHEAD, h = bh % NHEAD;
    int tid = threadIdx.x;
    int wid = tid >> 5, lid = tid & 31;

    __shared__ float qs[TOK][DHEAD + 1];
    __shared__ float ks[TOK][DHEAD + 1];
    __shared__ float vs[TOK][DHEAD + 1];
    __shared__ float ps[TOK][TOK + 1];

    for (int e = tid; e < TOK * DHEAD; e += 256) {
        int t = e / DHEAD, d = e % DHEAD;
        size_t rb = (size_t)(b * TOK + t) * (3 * DIMSZ) + (size_t)h * DHEAD + d;
        qs[t][d] = g_qkv[rb];
        ks[t][d] = g_qkv[rb + DIMSZ];
        vs[t][d] = g_qkv[rb + 2 * DIMSZ];
    }
    __syncthreads();

    for (int e = tid; e < TOK * TOK; e += 256) {
        int q = e / TOK, j = e % TOK;
        float acc = 0.f;
        #pragma unroll
        for (int d = 0; d < DHEAD; d++) acc += qs[q][d] * ks[j][d];
        ps[q][j] = acc * 0.125f;
    }
    __syncthreads();

    for (int row = wid; row < TOK; row += 8) {
        float mx = -1e30f;
        for (int j = lid; j < TOK; j += 32) mx = fmaxf(mx, ps[row][j]);
        #pragma unroll
        for (int o = 16; o; o >>= 1) mx = fmaxf(mx, __shfl_xor_sync(0xffffffffu, mx, o));
        float sum = 0.f, e0 = 0.f, e1 = 0.f;
        if (lid < TOK)      { e0 = expf(ps[row][lid] - mx);      sum += e0; }
        if (lid + 32 < TOK) { e1 = expf(ps[row][lid + 32] - mx); sum += e1; }
        #pragma unroll
        for (int o = 16; o; o >>= 1) sum += __shfl_xor_sync(0xffffffffu, sum, o);
        float inv = 1.f / sum;
        if (lid < TOK)      ps[row][lid]      = e0 * inv;
        if (lid + 32 < TOK) ps[row][lid + 32] = e1 * inv;
    }
    __syncthreads();

    for (int e = tid; e < TOK * DHEAD; e += 256) {
        int q = e / DHEAD, d = e % DHEAD;
        float acc = 0.f;
        #pragma unroll
        for (int j = 0; j < TOK; j++) acc += ps[q][j] * vs[j][d];
        size_t ob = (size_t)(b * TOK + q) * DIMSZ + (size_t)h * DHEAD + d;
        __nv_bfloat16 hi, lo;
        split1(acc, hi, lo);
        g_ath[ob] = hi;
        g_atl[ob] = lo;
    }
}

// ---------------- launcher ---------------------------------------------------
extern "C" void kernel_launch(void* const* d_in, const int* in_sizes, int n_in,
                              void* d_out, int out_size)
{
    const float* inputs  = (const float*)d_in[0];
    const float* conv_w  = (const float*)d_in[1];
    const float* pe      = (const float*)d_in[3];
    const float* ln1_s   = (const float*)d_in[4];
    const float* ln1_b   = (const float*)d_in[5];
    const float* qkv_w   = (const float*)d_in[6];
    const float* proj_w  = (const float*)d_in[7];
    const float* ln2_s   = (const float*)d_in[8];
    const float* ln2_b   = (const float*)d_in[9];
    const float* w1      = (const float*)d_in[10];
    const float* b1      = (const float*)d_in[11];
    const float* w2      = (const float*)d_in[12];
    const float* b2      = (const float*)d_in[13];
    const int*   mask_idx= (const int*)  d_in[14];
    float* out = (float*)d_out;

    cudaFuncSetAttribute((const void*)gemm_mma128<0,0>, cudaFuncAttributeMaxDynamicSharedMemorySize, SMEM_GEMM);
    cudaFuncSetAttribute((const void*)gemm_mma128<2,0>, cudaFuncAttributeMaxDynamicSharedMemorySize, SMEM_GEMM);
    cudaFuncSetAttribute((const void*)gemm_mma128<0,1>, cudaFuncAttributeMaxDynamicSharedMemorySize, SMEM_GEMM);

    float *xbuf, *qkvbuf, *part;
    __nv_bfloat16 *hh, *hl, *ath, *atl, *fh, *fl, *wh, *wl;
    cudaGetSymbolAddress((void**)&xbuf,  g_x);
    cudaGetSymbolAddress((void**)&qkvbuf,g_qkv);
    cudaGetSymbolAddress((void**)&part,  g_part);
    cudaGetSymbolAddress((void**)&hh,  g_hh);
    cudaGetSymbolAddress((void**)&hl,  g_hl);
    cudaGetSymbolAddress((void**)&ath, g_ath);
    cudaGetSymbolAddress((void**)&atl, g_atl);
    cudaGetSymbolAddress((void**)&fh,  g_fh);
    cudaGetSymbolAddress((void**)&fl,  g_fl);
    cudaGetSymbolAddress((void**)&wh,  g_wh);
    cudaGetSymbolAddress((void**)&wl,  g_wl);

    dim3 gsk(DIMSZ / 128, MPAD / 128, 2);    // (6, 25, 2) split-K N=768 GEMMs
    dim3 gqkv(3 * DIMSZ / 128, MPAD / 128);  // (18, 25)
    dim3 gff1(FFSZ / 128, MPAD / 128);       // (24, 25)
    const int RED_BLOCKS = (MTOK * DIMSZ / 4 + 255) / 256;

    // order: ncu's #6 == our #4 == conv split-K GEMM (control vs R10)
    split_a_kernel<<<((size_t)OFF_PROJ/8 + 255)/256, 256>>>(conv_w, qkv_w);
    split_b_kernel<<<(((size_t)WTOTAL - OFF_PROJ)/8 + 255)/256, 256>>>(proj_w, w1, w2);
    gather_patches_kernel<<<MTOK, 256>>>(inputs, mask_idx);
    gemm_mma128<0,1><<<gsk, 256, SMEM_GEMM>>>(ath, atl, wh + OFF_CONV, wl + OFF_CONV,
                nullptr, part, nullptr, nullptr, MPAD, DIMSZ, DIMSZ);
    // fused: reduce(+pe) -> x, then LN1(layer0) -> hh/hl
    reduce_ln_kernel<0><<<MTOK, 192>>>(nullptr, pe, mask_idx,
                                       ln1_s, ln1_b, xbuf, hh, hl);

    for (int l = 0; l < DEPTH; l++) {
        gemm_mma128<0,0><<<gqkv, 256, SMEM_GEMM>>>(hh, hl,
                    wh + OFF_QKV + (size_t)l * DIMSZ * 3 * DIMSZ,
                    wl + OFF_QKV + (size_t)l * DIMSZ * 3 * DIMSZ,
                    nullptr, qkvbuf, nullptr, nullptr,
                    MPAD, 3 * DIMSZ, DIMSZ);

        attention_kernel<<<BATCH * NHEAD, 256>>>();

        gemm_mma128<0,1><<<gsk, 256, SMEM_GEMM>>>(ath, atl,
                    wh + OFF_PROJ + (size_t)l * DIMSZ * DIMSZ,
                    wl + OFF_PROJ + (size_t)l * DIMSZ * DIMSZ,
                    nullptr, part, nullptr, nullptr, MPAD, DIMSZ, DIMSZ);
        // fused: reduce(+x) -> x, then LN2 -> hh/hl
        reduce_ln_kernel<1><<<MTOK, 192>>>(nullptr, nullptr, nullptr,
                    ln2_s + (size_t)l * DIMSZ, ln2_b + (size_t)l * DIMSZ,
                    xbuf, hh, hl);

        gemm_mma128<2,0><<<gff1, 256, SMEM_GEMM>>>(hh, hl,
                    wh + OFF_W1 + (size_t)l * DIMSZ * FFSZ,
                    wl + OFF_W1 + (size_t)l * DIMSZ * FFSZ,
                    b1 + (size_t)l * FFSZ, nullptr, fh, fl,
                    MPAD, FFSZ, DIMSZ);

        gemm_mma128<0,1><<<gsk, 256, SMEM_GEMM>>>(fh, fl,
                    wh + OFF_W2 + (size_t)l * FFSZ * DIMSZ,
                    wl + OFF_W2 + (size_t)l * FFSZ * DIMSZ,
                    nullptr, part, nullptr, nullptr, MPAD, DIMSZ, FFSZ);
        if (l == DEPTH - 1) {
            reduce_final_kernel<<<RED_BLOCKS, 256>>>(b2 + (size_t)l * DIMSZ, xbuf, out);
        } else {
            // fused: reduce(+b2 +x) -> x, then LN1(layer l+1) -> hh/hl
            reduce_ln_kernel<2><<<MTOK, 192>>>(b2 + (size_t)l * DIMSZ, nullptr, nullptr,
                        ln1_s + (size_t)(l + 1) * DIMSZ, ln1_b + (size_t)(l + 1) * DIMSZ,
                        xbuf, hh, hl);
        }
    }
}